// round 4
// baseline (speedup 1.0000x reference)
#include <cuda_runtime.h>
#include <cuda_bf16.h>
#include <cstdint>

// Problem constants (BuseE): N_ENT=200000, N_REL=500, DIM=64, B=1024, NC=1024
#define N_ENT 200000
#define BQ    1024
#define NC    1024
#define MARGIN 9.0f
#define EPS 1e-15f

#define TAIL_BLOCKS (N_ENT / 32)   // 6250 (32 rows / 256-thr block)
#define HEAD_BLOCKS (BQ / 8)       // 128  (8 heads / 256-thr block)
#define SEGS 8                     // score blocks per b-row
#define CPB (NC / SEGS)            // 128 candidates per score block

// ---------------- device scratch (allocation-free) ----------------
// tail rows as bf16: 200000 * 64 * 2B = 25.6MB, row = 8 x uint4 (16B each)
__device__ uint4  g_tail[N_ENT * 8];
// per-entity: {t2 = ||tail||^2, log(max(1-t2,eps)), bias_tail, pad}
__device__ float4 g_tab[N_ENT];
// per-b transformed head scaled by 2 (fp32, 64 dims)
__device__ float  g_head[BQ * 64];
// per-b: {A, sig, hh, pad}
__device__ float4 g_rowc[BQ];

// ---------------- fast math helpers -------------------------------
__device__ __forceinline__ float tanh_approx(float x) {
    float r;
    asm("tanh.approx.f32 %0, %1;" : "=f"(r) : "f"(x));
    return r;
}

__device__ __forceinline__ float wsum32(float v) {
    #pragma unroll
    for (int m = 16; m; m >>= 1) v += __shfl_xor_sync(0xffffffffu, v, m);
    return v;
}

// ---------------- head transform primitives (warp-per-row) --------
__device__ __forceinline__ float2 expmap0_w(float2 v) {
    float n2   = wsum32(v.x * v.x + v.y * v.y);
    float rinv = rsqrtf(fmaxf(n2, 1e-36f));
    float un   = fmaxf(n2 * rinv, EPS);      // = max(||v||, eps)
    float f    = tanh_approx(un) * rinv;     // tanh(un)/un
    return make_float2(f * v.x, f * v.y);
}

__device__ __forceinline__ float2 mobius_w(float2 x, float2 y) {
    float x2 = wsum32(x.x * x.x + x.y * x.y);
    float y2 = wsum32(y.x * y.x + y.y * y.y);
    float xy = wsum32(x.x * y.x + x.y * y.y);
    float a   = 1.f + 2.f * xy + y2;
    float bq  = 1.f - x2;
    float inv = 1.f / fmaxf(1.f + 2.f * xy + x2 * y2, EPS);
    return make_float2((a * x.x + bq * y.x) * inv,
                       (a * x.y + bq * y.y) * inv);
}

// ---------------- fused prep kernel -------------------------------
__global__ void __launch_bounds__(256) prep_kernel(
    const int* __restrict__ u_idx, const int* __restrict__ r_idx,
    const float* __restrict__ emb, const float* __restrict__ rel_diag,
    const float* __restrict__ rb1, const float* __restrict__ rb2,
    const float* __restrict__ bias_head, const float* __restrict__ bias_tail,
    const float* __restrict__ sigma)
{
    if (blockIdx.x < TAIL_BLOCKS) {
        // ---- tail path: 8 lanes per entity row (32 rows / block) ----
        int row = blockIdx.x * 32 + (threadIdx.x >> 3);
        int s   = threadIdx.x & 7;

        const float4* e4 = reinterpret_cast<const float4*>(emb) + (size_t)row * 16;
        float4 a = e4[s * 2];
        float4 c = e4[s * 2 + 1];
        float p = a.x * a.x + a.y * a.y + a.z * a.z + a.w * a.w
                + c.x * c.x + c.y * c.y + c.z * c.z + c.w * c.w;
        #pragma unroll
        for (int m = 4; m; m >>= 1) p += __shfl_xor_sync(0xffffffffu, p, m);

        float rinv = rsqrtf(fmaxf(p, 1e-36f));
        float un   = fmaxf(p * rinv, EPS);
        float f    = tanh_approx(un) * rinv;        // tanh(||u||)/||u||

        __nv_bfloat162 b0 = __floats2bfloat162_rn(f * a.x, f * a.y);
        __nv_bfloat162 b1 = __floats2bfloat162_rn(f * a.z, f * a.w);
        __nv_bfloat162 b2 = __floats2bfloat162_rn(f * c.x, f * c.y);
        __nv_bfloat162 b3 = __floats2bfloat162_rn(f * c.z, f * c.w);
        uint4 o;
        o.x = *reinterpret_cast<unsigned int*>(&b0);
        o.y = *reinterpret_cast<unsigned int*>(&b1);
        o.z = *reinterpret_cast<unsigned int*>(&b2);
        o.w = *reinterpret_cast<unsigned int*>(&b3);
        g_tail[(size_t)row * 8 + s] = o;

        if (s == 0) {
            float t  = tanh_approx(un);
            float t2 = t * t;                        // ||expmap0(u)||^2
            g_tab[row] = make_float4(t2, __logf(fmaxf(1.f - t2, EPS)),
                                     bias_tail[row], 0.f);
        }
    } else {
        // ---- head path: 1 warp per b-row (8 rows / block) ----
        int b    = (blockIdx.x - TAIL_BLOCKS) * 8 + (threadIdx.x >> 5);
        int lane = threadIdx.x & 31;
        int u = u_idx[b];
        int r = r_idx[b];

        float2 h  = expmap0_w(reinterpret_cast<const float2*>(emb + (size_t)u * 64)[lane]);
        float2 y1 = expmap0_w(reinterpret_cast<const float2*>(rb1 + (size_t)r * 64)[lane]);
        h = mobius_w(h, y1);

        float2 g  = reinterpret_cast<const float2*>(rel_diag + (size_t)r * 64)[lane];
        float gri = rsqrtf(fmaxf(g.x * g.x + g.y * g.y, 1e-36f));
        float gx = g.x * gri, gy = g.y * gri;
        float2 rot = make_float2(gx * h.x - gy * h.y, gy * h.x + gx * h.y);

        float2 y2 = expmap0_w(reinterpret_cast<const float2*>(rb2 + (size_t)r * 64)[lane]);
        h = mobius_w(rot, y2);

        float hh = wsum32(h.x * h.x + h.y * h.y);
        // store 2*h so the scoring dot yields 2*(head . tail) directly
        reinterpret_cast<float2*>(g_head + b * 64)[lane] =
            make_float2(2.f * h.x, 2.f * h.y);

        if (lane == 0) {
            float sg = 1.f / (1.f + __expf(-sigma[r]));
            float A  = MARGIN + bias_head[u]
                     + (1.f - sg) * __logf(fmaxf(1.f - hh, EPS));
            g_rowc[b] = make_float4(A, sg, hh, 0.f);
        }
    }
}

// ---------------- scoring (hot loop) ------------------------------
// 8 blocks per b-row; each warp owns exactly 16 candidates, issues all
// 12 gather loads up front (flat MLP), one reduce+epilogue burst, done.
// 8-lane group per element: one 128B row = one L1 line per element.
__device__ __forceinline__ float dot8(float4 ha, float4 hb, uint4 e) {
    float2 f0 = __bfloat1622float2(*reinterpret_cast<__nv_bfloat162*>(&e.x));
    float2 f1 = __bfloat1622float2(*reinterpret_cast<__nv_bfloat162*>(&e.y));
    float2 f2 = __bfloat1622float2(*reinterpret_cast<__nv_bfloat162*>(&e.z));
    float2 f3 = __bfloat1622float2(*reinterpret_cast<__nv_bfloat162*>(&e.w));
    float d0 = ha.x * f0.x;
    float d1 = ha.y * f0.y;
    d0 = fmaf(ha.z, f1.x, d0);
    d1 = fmaf(ha.w, f1.y, d1);
    d0 = fmaf(hb.x, f2.x, d0);
    d1 = fmaf(hb.y, f2.y, d1);
    d0 = fmaf(hb.z, f3.x, d0);
    d1 = fmaf(hb.w, f3.y, d1);
    return d0 + d1;
}

__global__ void __launch_bounds__(256) score_kernel(
    const int* __restrict__ v_idx, float* __restrict__ out)
{
    int b    = blockIdx.x >> 3;          // b-row
    int seg  = blockIdx.x & 7;           // candidate segment
    int lane = threadIdx.x & 31;
    int w    = threadIdx.x >> 5;         // warp 0..7
    int g    = lane >> 3;                // group 0..3
    int s    = lane & 7;                 // dim-chunk 0..7

    // warp owns candidates [cbase, cbase+16)
    int cbase = seg * CPB + w * 16;
    const int* vrow = v_idx + (size_t)b * NC;
    float*     orow = out   + (size_t)b * NC;

    // ---- issue every load up front (flat MLP ≈ 12) ----
    int c[4], v[4];
    #pragma unroll
    for (int k = 0; k < 4; k++) {
        c[k] = cbase + k * 4 + g;
        v[k] = __ldg(vrow + c[k]);
    }

    const float4* h4 = reinterpret_cast<const float4*>(g_head + b * 64);
    float4 ha = h4[s * 2];
    float4 hb = h4[s * 2 + 1];
    float4 rc = g_rowc[b];               // {A, sig, hh, _}

    uint4  e[4];
    float4 t[4];
    #pragma unroll
    for (int k = 0; k < 4; k++) e[k] = g_tail[(size_t)v[k] * 8 + s];
    #pragma unroll
    for (int k = 0; k < 4; k++) t[k] = g_tab[v[k]];

    // ---- compute ----
    float d[4];
    #pragma unroll
    for (int k = 0; k < 4; k++) d[k] = dot8(ha, hb, e[k]);  // = 2*(h.tail)

    #pragma unroll
    for (int m = 4; m; m >>= 1) {
        #pragma unroll
        for (int k = 0; k < 4; k++)
            d[k] += __shfl_xor_sync(0xffffffffu, d[k], m);
    }

    if (s == 0) {
        #pragma unroll
        for (int k = 0; k < 4; k++) {
            float num = rc.z + t[k].x - d[k];
            orow[c[k]] = rc.x - __logf(fmaxf(num, EPS))
                       + fmaf(rc.y, t[k].y, t[k].z);
        }
    }
}

// ---------------- launch ------------------------------------------
extern "C" void kernel_launch(void* const* d_in, const int* in_sizes, int n_in,
                              void* d_out, int out_size)
{
    const int*   u_idx     = (const int*)  d_in[0];
    const int*   r_idx     = (const int*)  d_in[1];
    const int*   v_idx     = (const int*)  d_in[2];
    const float* emb       = (const float*)d_in[3];
    const float* rel_diag  = (const float*)d_in[4];
    const float* rb1       = (const float*)d_in[5];
    const float* rb2       = (const float*)d_in[6];
    const float* bias_head = (const float*)d_in[7];
    const float* bias_tail = (const float*)d_in[8];
    const float* sigma     = (const float*)d_in[9];
    float* out = (float*)d_out;

    prep_kernel<<<TAIL_BLOCKS + HEAD_BLOCKS, 256>>>(
        u_idx, r_idx, emb, rel_diag, rb1, rb2, bias_head, bias_tail, sigma);
    score_kernel<<<BQ * SEGS, 256>>>(v_idx, out);
}

// round 8
// speedup vs baseline: 1.1992x; 1.1992x over previous
#include <cuda_runtime.h>
#include <cuda_bf16.h>
#include <cstdint>

// Problem constants (BuseE): N_ENT=200000, N_REL=500, DIM=64, B=1024, NC=1024
#define N_ENT 200000
#define BQ    1024
#define NC    1024
#define MARGIN 9.0f
#define EPS 1e-15f

#define TAIL_BLOCKS (N_ENT / 64)   // 3125 (64 rows / 256-thr block, 4 lanes/row)
#define HEAD_BLOCKS (BQ / 8)       // 128

// ---------------- device scratch (allocation-free) ----------------
// per-entity 128B line: [0,64) = 64 x int8 dims; [64,80) = float4 meta
// meta = { t2, log(max(1-t2,eps)), bias_tail, sc }
__device__ uint4 g_row[N_ENT * 8];          // 25.6 MB
// per-b quantized head: 64 x int8 = 16 words
__device__ unsigned g_headq[BQ * 16];
// per-b: { A, sig, hh, 2*sh/(127*127) }
__device__ float4 g_rowc[BQ];

// ---------------- fast math helpers -------------------------------
__device__ __forceinline__ float tanh_approx(float x) {
    float r;
    asm("tanh.approx.f32 %0, %1;" : "=f"(r) : "f"(x));
    return r;
}

__device__ __forceinline__ float wsum32(float v) {
    #pragma unroll
    for (int m = 16; m; m >>= 1) v += __shfl_xor_sync(0xffffffffu, v, m);
    return v;
}
__device__ __forceinline__ float wmax32(float v) {
    #pragma unroll
    for (int m = 16; m; m >>= 1)
        v = fmaxf(v, __shfl_xor_sync(0xffffffffu, v, m));
    return v;
}

// ---------------- head transform primitives (warp-per-row) --------
__device__ __forceinline__ float2 expmap0_w(float2 v) {
    float n2   = wsum32(v.x * v.x + v.y * v.y);
    float rinv = rsqrtf(fmaxf(n2, 1e-36f));
    float un   = fmaxf(n2 * rinv, EPS);
    float f    = tanh_approx(un) * rinv;
    return make_float2(f * v.x, f * v.y);
}

__device__ __forceinline__ float2 mobius_w(float2 x, float2 y) {
    float x2 = wsum32(x.x * x.x + x.y * x.y);
    float y2 = wsum32(y.x * y.x + y.y * y.y);
    float xy = wsum32(x.x * y.x + x.y * y.y);
    float a   = 1.f + 2.f * xy + y2;
    float bq  = 1.f - x2;
    float inv = 1.f / fmaxf(1.f + 2.f * xy + x2 * y2, EPS);
    return make_float2((a * x.x + bq * y.x) * inv,
                       (a * x.y + bq * y.y) * inv);
}

__device__ __forceinline__ unsigned pack4(float a, float b, float c, float d,
                                          float fi) {
    int q0 = __float2int_rn(a * fi);
    int q1 = __float2int_rn(b * fi);
    int q2 = __float2int_rn(c * fi);
    int q3 = __float2int_rn(d * fi);
    return (q0 & 0xFF) | ((q1 & 0xFF) << 8) | ((q2 & 0xFF) << 16)
         | ((unsigned)(q3 & 0xFF) << 24);
}

// ---------------- fused prep kernel -------------------------------
__global__ void __launch_bounds__(256) prep_kernel(
    const int* __restrict__ u_idx, const int* __restrict__ r_idx,
    const float* __restrict__ emb, const float* __restrict__ rel_diag,
    const float* __restrict__ rb1, const float* __restrict__ rb2,
    const float* __restrict__ bias_head, const float* __restrict__ bias_tail,
    const float* __restrict__ sigma)
{
    if (blockIdx.x < TAIL_BLOCKS) {
        // ---- tail path: 4 lanes per entity row (64 rows / block) ----
        int row = blockIdx.x * 64 + (threadIdx.x >> 2);
        int s   = threadIdx.x & 3;        // lane covers dims [s*16, s*16+16)

        const float4* e4 = reinterpret_cast<const float4*>(emb) + (size_t)row * 16;
        float4 a = e4[s * 4 + 0];
        float4 b = e4[s * 4 + 1];
        float4 c = e4[s * 4 + 2];
        float4 d = e4[s * 4 + 3];

        float p = a.x*a.x + a.y*a.y + a.z*a.z + a.w*a.w
                + b.x*b.x + b.y*b.y + b.z*b.z + b.w*b.w
                + c.x*c.x + c.y*c.y + c.z*c.z + c.w*c.w
                + d.x*d.x + d.y*d.y + d.z*d.z + d.w*d.w;
        float am = fmaxf(fmaxf(fmaxf(fabsf(a.x), fabsf(a.y)),
                               fmaxf(fabsf(a.z), fabsf(a.w))),
                   fmaxf(fmaxf(fabsf(b.x), fabsf(b.y)),
                         fmaxf(fabsf(b.z), fabsf(b.w))));
        am = fmaxf(am, fmaxf(fmaxf(fabsf(c.x), fabsf(c.y)),
                             fmaxf(fabsf(c.z), fabsf(c.w))));
        am = fmaxf(am, fmaxf(fmaxf(fabsf(d.x), fabsf(d.y)),
                             fmaxf(fabsf(d.z), fabsf(d.w))));
        #pragma unroll
        for (int m = 2; m; m >>= 1) {
            p  += __shfl_xor_sync(0xffffffffu, p, m);
            am  = fmaxf(am, __shfl_xor_sync(0xffffffffu, am, m));
        }

        float rinv = rsqrtf(fmaxf(p, 1e-36f));
        float un   = fmaxf(p * rinv, EPS);
        float f    = tanh_approx(un) * rinv;   // tail = f * u
        float sc   = f * am;                   // max |tail_i|
        float fi   = 127.f * f / fmaxf(sc, 1e-30f);

        uint4 o;
        o.x = pack4(a.x, a.y, a.z, a.w, fi);
        o.y = pack4(b.x, b.y, b.z, b.w, fi);
        o.z = pack4(c.x, c.y, c.z, c.w, fi);
        o.w = pack4(d.x, d.y, d.z, d.w, fi);
        g_row[(size_t)row * 8 + s] = o;

        if (s == 0) {
            float t  = tanh_approx(un);
            float t2 = t * t;
            float4 meta = make_float4(t2, __logf(fmaxf(1.f - t2, EPS)),
                                      bias_tail[row], sc);
            g_row[(size_t)row * 8 + 4] = *reinterpret_cast<uint4*>(&meta);
        }
    } else {
        // ---- head path: 1 warp per b-row (8 rows / block) ----
        int b    = (blockIdx.x - TAIL_BLOCKS) * 8 + (threadIdx.x >> 5);
        int lane = threadIdx.x & 31;
        int u = u_idx[b];
        int r = r_idx[b];

        float2 h  = expmap0_w(reinterpret_cast<const float2*>(emb + (size_t)u * 64)[lane]);
        float2 y1 = expmap0_w(reinterpret_cast<const float2*>(rb1 + (size_t)r * 64)[lane]);
        h = mobius_w(h, y1);

        float2 g  = reinterpret_cast<const float2*>(rel_diag + (size_t)r * 64)[lane];
        float gri = rsqrtf(fmaxf(g.x * g.x + g.y * g.y, 1e-36f));
        float gx = g.x * gri, gy = g.y * gri;
        float2 rot = make_float2(gx * h.x - gy * h.y, gy * h.x + gx * h.y);

        float2 y2 = expmap0_w(reinterpret_cast<const float2*>(rb2 + (size_t)r * 64)[lane]);
        h = mobius_w(rot, y2);

        float hh = wsum32(h.x * h.x + h.y * h.y);
        float sh = fmaxf(wmax32(fmaxf(fabsf(h.x), fabsf(h.y))), 1e-30f);
        float inv = 127.f / sh;

        int q0 = __float2int_rn(h.x * inv);
        int q1 = __float2int_rn(h.y * inv);
        unsigned pk = (q0 & 0xFF) | ((q1 & 0xFF) << 8);
        unsigned other = __shfl_xor_sync(0xffffffffu, pk, 1);
        if ((lane & 1) == 0)
            g_headq[b * 16 + (lane >> 1)] = (pk & 0xFFFFu) | (other << 16);

        if (lane == 0) {
            float sg = 1.f / (1.f + __expf(-sigma[r]));
            float A  = MARGIN + bias_head[u]
                     + (1.f - sg) * __logf(fmaxf(1.f - hh, EPS));
            g_rowc[b] = make_float4(A, sg, hh, 2.f * sh / 16129.f);
        }
    }
}

// ---------------- scoring (hot loop) ------------------------------
// Warp owns 16 candidates. 8-lane group per element: lanes s<4 hold the
// int8 dims (16 each), lane s==4 holds the float4 meta — all from ONE
// 128B line via one predicated LDG.128. DP4A dot, shuffle reduce, lane
// s==4 runs the epilogue and stores.
__global__ void __launch_bounds__(256) score_kernel(
    const int* __restrict__ v_idx, float* __restrict__ out)
{
    int w    = threadIdx.x >> 5;
    int gw   = blockIdx.x * 8 + w;       // global warp id
    int b    = gw >> 6;                  // b-row (64 warps per row)
    int seg  = gw & 63;
    int lane = threadIdx.x & 31;
    int g    = lane >> 3;                // group 0..3
    int s    = lane & 7;                 // slot in group

    int cbase = seg * 16;
    const int* vrow = v_idx + (size_t)b * NC;
    float*     orow = out   + (size_t)b * NC;

    // head chunk for this slot (s<4 meaningful)
    uint4 hq = reinterpret_cast<const uint4*>(g_headq)[b * 4 + (s & 3)];
    float4 rc = g_rowc[b];               // {A, sig, hh, 2*sh/127^2}

    // ---- flat gather: 4 idx + 4 payload lines ----
    int v[4];
    #pragma unroll
    for (int j = 0; j < 4; j++)
        v[j] = __ldg(vrow + cbase + j * 4 + g);

    uint4 p[4];
    #pragma unroll
    for (int j = 0; j < 4; j++) {
        p[j] = make_uint4(0u, 0u, 0u, 0u);
        if (s < 5) p[j] = g_row[(size_t)v[j] * 8 + s];
    }

    // ---- integer dot ----
    int I[4];
    #pragma unroll
    for (int j = 0; j < 4; j++) {
        int acc = 0;
        if (s < 4) {
            acc = __dp4a((int)p[j].x, (int)hq.x, acc);
            acc = __dp4a((int)p[j].y, (int)hq.y, acc);
            acc = __dp4a((int)p[j].z, (int)hq.z, acc);
            acc = __dp4a((int)p[j].w, (int)hq.w, acc);
        }
        I[j] = acc;
    }

    #pragma unroll
    for (int m = 1; m <= 4; m <<= 1) {
        #pragma unroll
        for (int j = 0; j < 4; j++)
            I[j] += __shfl_xor_sync(0xffffffffu, I[j], m);
    }

    // ---- epilogue on meta lane ----
    if (s == 4) {
        #pragma unroll
        for (int j = 0; j < 4; j++) {
            float4 mt = *reinterpret_cast<float4*>(&p[j]);  // {t2,l,bias,sc}
            float K   = rc.w * mt.w;
            float num = fmaxf(rc.z + mt.x - K * (float)I[j], EPS);
            float E   = rc.x + fmaf(rc.y, mt.y, mt.z);
            orow[cbase + j * 4 + g] = E - __logf(num);
        }
    }
}

// ---------------- launch ------------------------------------------
extern "C" void kernel_launch(void* const* d_in, const int* in_sizes, int n_in,
                              void* d_out, int out_size)
{
    const int*   u_idx     = (const int*)  d_in[0];
    const int*   r_idx     = (const int*)  d_in[1];
    const int*   v_idx     = (const int*)  d_in[2];
    const float* emb       = (const float*)d_in[3];
    const float* rel_diag  = (const float*)d_in[4];
    const float* rb1       = (const float*)d_in[5];
    const float* rb2       = (const float*)d_in[6];
    const float* bias_head = (const float*)d_in[7];
    const float* bias_tail = (const float*)d_in[8];
    const float* sigma     = (const float*)d_in[9];
    float* out = (float*)d_out;

    prep_kernel<<<TAIL_BLOCKS + HEAD_BLOCKS, 256>>>(
        u_idx, r_idx, emb, rel_diag, rb1, rb2, bias_head, bias_tail, sigma);
    // 1M elements / (8 warps * 16 elem) = 8192 blocks
    score_kernel<<<(BQ * NC) / 128, 256>>>(v_idx, out);
}

// round 10
// speedup vs baseline: 1.2029x; 1.0031x over previous
#include <cuda_runtime.h>
#include <cuda_bf16.h>
#include <cstdint>

// Problem constants (BuseE): N_ENT=200000, N_REL=500, DIM=64, B=1024, NC=1024
#define N_ENT 200000
#define BQ    1024
#define NC    1024
#define MARGIN 9.0f
#define EPS 1e-15f

#define TAIL_BLOCKS (N_ENT / 64)   // 3125 (64 rows / 256-thr block, 4 lanes/row)
#define HEAD_BLOCKS (BQ / 8)       // 128

// ---------------- device scratch (allocation-free) ----------------
// per-entity 128B line: [0,64) = 64 x int8 dims; [64,80) = float4 meta
// meta = { t2, log(max(1-t2,eps)), bias_tail, sc }
__device__ uint4 g_row[N_ENT * 8];          // 25.6 MB
// per-b quantized head: 64 x int8 = 16 words
__device__ unsigned g_headq[BQ * 16];
// per-b: { A, sig, hh, 2*sh/(127*127) }
__device__ float4 g_rowc[BQ];

// ---------------- fast math helpers -------------------------------
__device__ __forceinline__ float tanh_approx(float x) {
    float r;
    asm("tanh.approx.f32 %0, %1;" : "=f"(r) : "f"(x));
    return r;
}

__device__ __forceinline__ float wsum32(float v) {
    #pragma unroll
    for (int m = 16; m; m >>= 1) v += __shfl_xor_sync(0xffffffffu, v, m);
    return v;
}
__device__ __forceinline__ float wmax32(float v) {
    #pragma unroll
    for (int m = 16; m; m >>= 1)
        v = fmaxf(v, __shfl_xor_sync(0xffffffffu, v, m));
    return v;
}

// ---------------- head transform primitives (warp-per-row) --------
__device__ __forceinline__ float2 expmap0_w(float2 v) {
    float n2   = wsum32(v.x * v.x + v.y * v.y);
    float rinv = rsqrtf(fmaxf(n2, 1e-36f));
    float un   = fmaxf(n2 * rinv, EPS);
    float f    = tanh_approx(un) * rinv;
    return make_float2(f * v.x, f * v.y);
}

__device__ __forceinline__ float2 mobius_w(float2 x, float2 y) {
    float x2 = wsum32(x.x * x.x + x.y * x.y);
    float y2 = wsum32(y.x * y.x + y.y * y.y);
    float xy = wsum32(x.x * y.x + x.y * y.y);
    float a   = 1.f + 2.f * xy + y2;
    float bq  = 1.f - x2;
    float inv = 1.f / fmaxf(1.f + 2.f * xy + x2 * y2, EPS);
    return make_float2((a * x.x + bq * y.x) * inv,
                       (a * x.y + bq * y.y) * inv);
}

__device__ __forceinline__ unsigned pack4(float a, float b, float c, float d,
                                          float fi) {
    int q0 = __float2int_rn(a * fi);
    int q1 = __float2int_rn(b * fi);
    int q2 = __float2int_rn(c * fi);
    int q3 = __float2int_rn(d * fi);
    return (q0 & 0xFF) | ((q1 & 0xFF) << 8) | ((q2 & 0xFF) << 16)
         | ((unsigned)(q3 & 0xFF) << 24);
}

// ---------------- fused prep kernel -------------------------------
__global__ void __launch_bounds__(256) prep_kernel(
    const int* __restrict__ u_idx, const int* __restrict__ r_idx,
    const float* __restrict__ emb, const float* __restrict__ rel_diag,
    const float* __restrict__ rb1, const float* __restrict__ rb2,
    const float* __restrict__ bias_head, const float* __restrict__ bias_tail,
    const float* __restrict__ sigma)
{
    if (blockIdx.x < TAIL_BLOCKS) {
        // ---- tail path: 4 lanes per entity row (64 rows / block) ----
        int row = blockIdx.x * 64 + (threadIdx.x >> 2);
        int s   = threadIdx.x & 3;        // lane covers dims [s*16, s*16+16)

        const float4* e4 = reinterpret_cast<const float4*>(emb) + (size_t)row * 16;
        float4 a = e4[s * 4 + 0];
        float4 b = e4[s * 4 + 1];
        float4 c = e4[s * 4 + 2];
        float4 d = e4[s * 4 + 3];

        float p = a.x*a.x + a.y*a.y + a.z*a.z + a.w*a.w
                + b.x*b.x + b.y*b.y + b.z*b.z + b.w*b.w
                + c.x*c.x + c.y*c.y + c.z*c.z + c.w*c.w
                + d.x*d.x + d.y*d.y + d.z*d.z + d.w*d.w;
        float am = fmaxf(fmaxf(fmaxf(fabsf(a.x), fabsf(a.y)),
                               fmaxf(fabsf(a.z), fabsf(a.w))),
                   fmaxf(fmaxf(fabsf(b.x), fabsf(b.y)),
                         fmaxf(fabsf(b.z), fabsf(b.w))));
        am = fmaxf(am, fmaxf(fmaxf(fabsf(c.x), fabsf(c.y)),
                             fmaxf(fabsf(c.z), fabsf(c.w))));
        am = fmaxf(am, fmaxf(fmaxf(fabsf(d.x), fabsf(d.y)),
                             fmaxf(fabsf(d.z), fabsf(d.w))));
        #pragma unroll
        for (int m = 2; m; m >>= 1) {
            p  += __shfl_xor_sync(0xffffffffu, p, m);
            am  = fmaxf(am, __shfl_xor_sync(0xffffffffu, am, m));
        }

        float rinv = rsqrtf(fmaxf(p, 1e-36f));
        float un   = fmaxf(p * rinv, EPS);
        float f    = tanh_approx(un) * rinv;   // tail = f * u
        float sc   = f * am;                   // max |tail_i|
        float fi   = 127.f * f / fmaxf(sc, 1e-30f);

        uint4 o;
        o.x = pack4(a.x, a.y, a.z, a.w, fi);
        o.y = pack4(b.x, b.y, b.z, b.w, fi);
        o.z = pack4(c.x, c.y, c.z, c.w, fi);
        o.w = pack4(d.x, d.y, d.z, d.w, fi);
        g_row[(size_t)row * 8 + s] = o;

        if (s == 0) {
            float t  = tanh_approx(un);
            float t2 = t * t;
            float4 meta = make_float4(t2, __logf(fmaxf(1.f - t2, EPS)),
                                      bias_tail[row], sc);
            g_row[(size_t)row * 8 + 4] = *reinterpret_cast<uint4*>(&meta);
        }
    } else {
        // ---- head path: 1 warp per b-row (8 rows / block) ----
        int b    = (blockIdx.x - TAIL_BLOCKS) * 8 + (threadIdx.x >> 5);
        int lane = threadIdx.x & 31;
        int u = u_idx[b];
        int r = r_idx[b];

        float2 h  = expmap0_w(reinterpret_cast<const float2*>(emb + (size_t)u * 64)[lane]);
        float2 y1 = expmap0_w(reinterpret_cast<const float2*>(rb1 + (size_t)r * 64)[lane]);
        h = mobius_w(h, y1);

        float2 g  = reinterpret_cast<const float2*>(rel_diag + (size_t)r * 64)[lane];
        float gri = rsqrtf(fmaxf(g.x * g.x + g.y * g.y, 1e-36f));
        float gx = g.x * gri, gy = g.y * gri;
        float2 rot = make_float2(gx * h.x - gy * h.y, gy * h.x + gx * h.y);

        float2 y2 = expmap0_w(reinterpret_cast<const float2*>(rb2 + (size_t)r * 64)[lane]);
        h = mobius_w(rot, y2);

        float hh = wsum32(h.x * h.x + h.y * h.y);
        float sh = fmaxf(wmax32(fmaxf(fabsf(h.x), fabsf(h.y))), 1e-30f);
        float inv = 127.f / sh;

        int q0 = __float2int_rn(h.x * inv);
        int q1 = __float2int_rn(h.y * inv);
        unsigned pk = (q0 & 0xFF) | ((q1 & 0xFF) << 8);
        unsigned other = __shfl_xor_sync(0xffffffffu, pk, 1);
        if ((lane & 1) == 0)
            g_headq[b * 16 + (lane >> 1)] = (pk & 0xFFFFu) | (other << 16);

        if (lane == 0) {
            float sg = 1.f / (1.f + __expf(-sigma[r]));
            float A  = MARGIN + bias_head[u]
                     + (1.f - sg) * __logf(fmaxf(1.f - hh, EPS));
            g_rowc[b] = make_float4(A, sg, hh, 2.f * sh / 16129.f);
        }
    }
}

// ---------------- scoring (hot loop) ------------------------------
// Warp owns 16 candidates; 8-lane group g owns candidates
// [cbase+4g, cbase+4g+4) so its indices arrive as ONE int4 (LDG.128)
// and its 4 results leave as ONE float4 (STG.128 on the meta lane).
// Lanes s<4 hold int8 dims, lane s==4 holds float4 meta — one 128B line
// per element. DP4A dot, 3-level shuffle reduce, epilogue on lane s==4.
__global__ void __launch_bounds__(128) score_kernel(
    const int* __restrict__ v_idx, float* __restrict__ out)
{
    int w    = threadIdx.x >> 5;
    int gw   = blockIdx.x * 4 + w;       // global warp id
    int b    = gw >> 6;                  // b-row (64 warps per row)
    int seg  = gw & 63;
    int lane = threadIdx.x & 31;
    int g    = lane >> 3;                // group 0..3
    int s    = lane & 7;                 // slot in group

    int cbase = seg * 16;
    const int4* vrow4 = reinterpret_cast<const int4*>(v_idx + (size_t)b * NC);
    float*      orow  = out + (size_t)b * NC;

    // head chunk for this slot (s<4 meaningful)
    uint4 hq = reinterpret_cast<const uint4*>(g_headq)[b * 4 + (s & 3)];
    float4 rc = g_rowc[b];               // {A, sig, hh, 2*sh/127^2}

    // ---- one vector idx load: group g's 4 candidates ----
    int4 V = __ldg(vrow4 + seg * 4 + g);
    int v[4] = { V.x, V.y, V.z, V.w };

    // ---- flat payload gather: 4 lines per group ----
    uint4 p[4];
    #pragma unroll
    for (int j = 0; j < 4; j++) {
        p[j] = make_uint4(0u, 0u, 0u, 0u);
        if (s < 5) p[j] = g_row[(size_t)v[j] * 8 + s];
    }

    // ---- integer dot ----
    int I[4];
    #pragma unroll
    for (int j = 0; j < 4; j++) {
        int acc = 0;
        if (s < 4) {
            acc = __dp4a((int)p[j].x, (int)hq.x, acc);
            acc = __dp4a((int)p[j].y, (int)hq.y, acc);
            acc = __dp4a((int)p[j].z, (int)hq.z, acc);
            acc = __dp4a((int)p[j].w, (int)hq.w, acc);
        }
        I[j] = acc;
    }

    #pragma unroll
    for (int m = 1; m <= 4; m <<= 1) {
        #pragma unroll
        for (int j = 0; j < 4; j++)
            I[j] += __shfl_xor_sync(0xffffffffu, I[j], m);
    }

    // ---- epilogue + one STG.128 on meta lane ----
    if (s == 4) {
        float res[4];
        #pragma unroll
        for (int j = 0; j < 4; j++) {
            float4 mt = *reinterpret_cast<float4*>(&p[j]);  // {t2,l,bias,sc}
            float K   = rc.w * mt.w;
            float num = fmaxf(rc.z + mt.x - K * (float)I[j], EPS);
            res[j]    = rc.x + fmaf(rc.y, mt.y, mt.z) - __logf(num);
        }
        *reinterpret_cast<float4*>(orow + cbase + 4 * g) =
            make_float4(res[0], res[1], res[2], res[3]);
    }
}

// ---------------- launch ------------------------------------------
extern "C" void kernel_launch(void* const* d_in, const int* in_sizes, int n_in,
                              void* d_out, int out_size)
{
    const int*   u_idx     = (const int*)  d_in[0];
    const int*   r_idx     = (const int*)  d_in[1];
    const int*   v_idx     = (const int*)  d_in[2];
    const float* emb       = (const float*)d_in[3];
    const float* rel_diag  = (const float*)d_in[4];
    const float* rb1       = (const float*)d_in[5];
    const float* rb2       = (const float*)d_in[6];
    const float* bias_head = (const float*)d_in[7];
    const float* bias_tail = (const float*)d_in[8];
    const float* sigma     = (const float*)d_in[9];
    float* out = (float*)d_out;

    prep_kernel<<<TAIL_BLOCKS + HEAD_BLOCKS, 256>>>(
        u_idx, r_idx, emb, rel_diag, rb1, rb2, bias_head, bias_tail, sigma);
    // 1M elements / (4 warps * 16 elem) = 16384 blocks
    score_kernel<<<(BQ * NC) / 64, 128>>>(v_idx, out);
}